// round 15
// baseline (speedup 1.0000x reference)
#include <cuda_runtime.h>
#include <cuda_fp16.h>
#include <stdint.h>

#define T_DIM 16384
#define H_DIM 4096
#define EPS 1e-5f

// ---------------------------------------------------------------------------
// Scratch (__device__ globals; allocation-free rule)
// ---------------------------------------------------------------------------
__device__ __align__(16) __half g_a [(size_t)T_DIM * H_DIM];  // 128 MB (A fp16)
__device__ __align__(16) float  g_r [(size_t)T_DIM * H_DIM];  // 256 MB
__device__ __align__(16) __half g_b [(size_t)H_DIM * H_DIM];  // 32 MB (B fp16)

// ---------------------------------------------------------------------------
// PTX helpers — family-portable only (ldmatrix / mma.sync / cp.async).
// tcgen05 is rejected by this harness's compute_103 PTX stage (R11 finding).
// ---------------------------------------------------------------------------
__device__ __forceinline__ uint32_t smem_to_u32(const void* p) {
    uint32_t a;
    asm("{ .reg .u64 t; cvta.to.shared.u64 t, %1; cvt.u32.u64 %0, t; }" : "=r"(a) : "l"(p));
    return a;
}
#define CP_ASYNC_16(dst, src) \
    asm volatile("cp.async.cg.shared.global [%0], [%1], 16;" :: "r"(dst), "l"(src))
#define CP_COMMIT() asm volatile("cp.async.commit_group;" ::: "memory")
#define CP_WAIT1()  asm volatile("cp.async.wait_group 1;" ::: "memory")
#define CP_WAIT0()  asm volatile("cp.async.wait_group 0;" ::: "memory")

__device__ __forceinline__ void ldmatrix_x4(uint32_t* r, uint32_t addr) {
    asm volatile("ldmatrix.sync.aligned.m8n8.x4.shared.b16 {%0,%1,%2,%3}, [%4];"
                 : "=r"(r[0]), "=r"(r[1]), "=r"(r[2]), "=r"(r[3]) : "r"(addr));
}
// fp16 MMA, fp32 accumulate
__device__ __forceinline__ void mma_16816(float* c, const uint32_t* a, const uint32_t* b) {
    asm volatile("mma.sync.aligned.m16n8k16.row.col.f32.f16.f16.f32 "
                 "{%0,%1,%2,%3}, {%4,%5,%6,%7}, {%8,%9}, {%0,%1,%2,%3};"
                 : "+f"(c[0]), "+f"(c[1]), "+f"(c[2]), "+f"(c[3])
                 : "r"(a[0]), "r"(a[1]), "r"(a[2]), "r"(a[3]), "r"(b[0]), "r"(b[1]));
}

// ---------------------------------------------------------------------------
// RMSNorm -> fp16 (A operand).
// ---------------------------------------------------------------------------
template<bool RELU_IN>
__global__ void __launch_bounds__(256) rmsnorm_h_kernel(
    const float* __restrict__ in, const float* __restrict__ g,
    __half* __restrict__ oh)
{
    const int row = blockIdx.x;
    const float4* inp = reinterpret_cast<const float4*>(in + (size_t)row * H_DIM);
    const float4* gp  = reinterpret_cast<const float4*>(g);
    uint2* hp = reinterpret_cast<uint2*>(oh + (size_t)row * H_DIM);

    float4 v[4];
    float ssq = 0.f;
    #pragma unroll
    for (int i = 0; i < 4; i++) {
        float4 t = inp[threadIdx.x + i * 256];
        if (RELU_IN) {
            t.x = fmaxf(t.x, 0.f); t.y = fmaxf(t.y, 0.f);
            t.z = fmaxf(t.z, 0.f); t.w = fmaxf(t.w, 0.f);
        }
        v[i] = t;
        ssq += t.x * t.x + t.y * t.y + t.z * t.z + t.w * t.w;
    }

    __shared__ float red[8];
    #pragma unroll
    for (int o = 16; o > 0; o >>= 1) ssq += __shfl_xor_sync(0xffffffffu, ssq, o);
    const int wid = threadIdx.x >> 5, lid = threadIdx.x & 31;
    if (lid == 0) red[wid] = ssq;
    __syncthreads();
    if (wid == 0) {
        float s = (lid < 8) ? red[lid] : 0.f;
        #pragma unroll
        for (int o = 4; o > 0; o >>= 1) s += __shfl_xor_sync(0xffffffffu, s, o);
        if (lid == 0) red[0] = rsqrtf(s * (1.0f / H_DIM) + EPS);
    }
    __syncthreads();
    const float rs = red[0];

    #pragma unroll
    for (int i = 0; i < 4; i++) {
        float4 gg = gp[threadIdx.x + i * 256];
        float4 t = v[i];
        t.x *= rs * gg.x; t.y *= rs * gg.y; t.z *= rs * gg.z; t.w *= rs * gg.w;
        __half h0 = __float2half_rn(t.x), h1 = __float2half_rn(t.y);
        __half h2 = __float2half_rn(t.z), h3 = __float2half_rn(t.w);
        uint2 uh;
        uh.x = (uint32_t)__half_as_ushort(h0) | ((uint32_t)__half_as_ushort(h1) << 16);
        uh.y = (uint32_t)__half_as_ushort(h2) | ((uint32_t)__half_as_ushort(h3) << 16);
        hp[threadIdx.x + i * 256] = uh;
    }
}

// Final RMSNorm -> fp32 out
__global__ void __launch_bounds__(256) rmsnorm_f32_kernel(
    const float* __restrict__ in, const float* __restrict__ g, float* __restrict__ out)
{
    const int row = blockIdx.x;
    const float4* inp  = reinterpret_cast<const float4*>(in + (size_t)row * H_DIM);
    float4*       outp = reinterpret_cast<float4*>(out + (size_t)row * H_DIM);
    const float4* gp   = reinterpret_cast<const float4*>(g);

    float4 v[4];
    float ssq = 0.f;
    #pragma unroll
    for (int i = 0; i < 4; i++) {
        float4 t = inp[threadIdx.x + i * 256];
        v[i] = t;
        ssq += t.x * t.x + t.y * t.y + t.z * t.z + t.w * t.w;
    }
    __shared__ float red[8];
    #pragma unroll
    for (int o = 16; o > 0; o >>= 1) ssq += __shfl_xor_sync(0xffffffffu, ssq, o);
    const int wid = threadIdx.x >> 5, lid = threadIdx.x & 31;
    if (lid == 0) red[wid] = ssq;
    __syncthreads();
    if (wid == 0) {
        float s = (lid < 8) ? red[lid] : 0.f;
        #pragma unroll
        for (int o = 4; o > 0; o >>= 1) s += __shfl_xor_sync(0xffffffffu, s, o);
        if (lid == 0) red[0] = rsqrtf(s * (1.0f / H_DIM) + EPS);
    }
    __syncthreads();
    const float rs = red[0];
    #pragma unroll
    for (int i = 0; i < 4; i++) {
        float4 gg = gp[threadIdx.x + i * 256];
        float4 t = v[i];
        t.x *= rs * gg.x; t.y *= rs * gg.y; t.z *= rs * gg.z; t.w *= rs * gg.w;
        outp[threadIdx.x + i * 256] = t;
    }
}

// ---------------------------------------------------------------------------
// Transpose -> fp16: Bt[n][k] = fp16(w[k][n]).
// ---------------------------------------------------------------------------
__global__ void __launch_bounds__(256) transpose_h_kernel(
    const float* __restrict__ w, __half* __restrict__ b)
{
    __shared__ float tile[32][33];
    const int x  = blockIdx.x * 32 + threadIdx.x;   // n
    const int y0 = blockIdx.y * 32 + threadIdx.y;   // k
    #pragma unroll
    for (int j = 0; j < 4; j++)
        tile[threadIdx.y + 8 * j][threadIdx.x] = w[(size_t)(y0 + 8 * j) * H_DIM + x];
    __syncthreads();
    const int xo = blockIdx.y * 32 + threadIdx.x;   // k
    const int yo = blockIdx.x * 32 + threadIdx.y;   // n
    #pragma unroll
    for (int j = 0; j < 4; j++) {
        float v = tile[threadIdx.x][threadIdx.y + 8 * j];
        b[(size_t)(yo + 8 * j) * H_DIM + xo] = __float2half_rn(v);
    }
}

// ---------------------------------------------------------------------------
// mma.sync fp16 GEMM: C[256x128 tile] = A @ B^T + addend, single pass.
//   MODE 0: addend = relu(addsrc);  MODE 1: addend = addsrc (in-place safe)
// 256 threads = 8 warps as 4M x 2N, warp tile 64x64 -> 8 LDSM.x4 per 32 MMA
// per k16 step (ratio 4.0 vs 2.67 at 32x64 warp tile). BK=64, 3-stage
// cp.async pipeline; stage = A(256x64, 32 KB) + B(128x64, 16 KB) = 48 KB,
// 3 stages = 144 KB, 1 CTA/SM. Smem rows 128 B xor-swizzled (chunk ^= row&7).
// ---------------------------------------------------------------------------
#define BKK 64
#define NCHUNK (H_DIM / BKK)            // 64
#define A_TILE_B 32768                  // 256 rows x 128 B
#define B_TILE_B 16384                  // 128 rows x 128 B
#define STAGE_B (A_TILE_B + B_TILE_B)   // 48 KB
#define STAGES 3
#define GEMM_SMEM_TOTAL (STAGES * STAGE_B)  // 147456

__device__ __forceinline__ void gemm_load_stage(
    uint32_t sbase, int slot, int k0, int tid, int rowBase, int colBase,
    const __half* A, const __half* B)
{
    const uint32_t stage_base = sbase + slot * STAGE_B;
    const char* asrc = (const char*)(A + (size_t)rowBase * H_DIM + k0);
    const char* bsrc = (const char*)(B + (size_t)colBase * H_DIM + k0);
    // A: 256 rows x 8 chunks = 2048 chunks, 8 per thread
    #pragma unroll
    for (int j = 0; j < 8; j++) {
        int idx = j * 256 + tid;
        int r = idx >> 3;
        int c = idx & 7;
        const char* src = asrc + (size_t)r * (H_DIM * 2) + c * 16;
        uint32_t dst = stage_base + r * 128 + ((c ^ (r & 7)) * 16);
        CP_ASYNC_16(dst, src);
    }
    // B: 128 rows x 8 chunks = 1024 chunks, 4 per thread
    #pragma unroll
    for (int j = 0; j < 4; j++) {
        int idx = j * 256 + tid;
        int r = idx >> 3;
        int c = idx & 7;
        const char* src = bsrc + (size_t)r * (H_DIM * 2) + c * 16;
        uint32_t dst = stage_base + A_TILE_B + r * 128 + ((c ^ (r & 7)) * 16);
        CP_ASYNC_16(dst, src);
    }
}

template<int MODE>
__global__ void __launch_bounds__(256, 1) gemm_mma_kernel(
    const __half* __restrict__ A, const __half* __restrict__ B,
    const float* addsrc, float* C)
{
    extern __shared__ char smem[];
    const uint32_t sbase = smem_to_u32(smem);
    const int tid  = threadIdx.x;
    const int lane = tid & 31;
    const int wid  = tid >> 5;
    const int warp_m = wid & 3;     // 0..3  (M, 64 rows each)
    const int warp_n = wid >> 2;    // 0..1  (N, 64 cols each)

    const int colBase = blockIdx.x * 128;
    const int rowBase = blockIdx.y * 256;

    float acc[4][8][4];
    #pragma unroll
    for (int mt = 0; mt < 4; mt++)
        #pragma unroll
        for (int nt = 0; nt < 8; nt++)
            #pragma unroll
            for (int q = 0; q < 4; q++) acc[mt][nt][q] = 0.f;

    gemm_load_stage(sbase, 0, 0,   tid, rowBase, colBase, A, B);
    CP_COMMIT();
    gemm_load_stage(sbase, 1, BKK, tid, rowBase, colBase, A, B);
    CP_COMMIT();

    for (int i = 0; i < NCHUNK; i++) {
        if (i + 1 < NCHUNK) { CP_WAIT1(); } else { CP_WAIT0(); }
        __syncthreads();
        if (i + 2 < NCHUNK) {
            gemm_load_stage(sbase, (i + 2) % STAGES, (i + 2) * BKK,
                            tid, rowBase, colBase, A, B);
            CP_COMMIT();
        }

        const uint32_t st = sbase + (i % STAGES) * STAGE_B;
        #pragma unroll
        for (int ks = 0; ks < 4; ks++) {        // four k16 steps in BK=64
            uint32_t a[4][4], b[8][2];

            // A fragments: rows warp_m*64 + mt*16; lanes 0-15 chunk ks*2,
            // lanes 16-31 chunk ks*2+1.
            const int arow0 = warp_m * 64 + (lane & 15);
            const int ac    = ks * 2 + (lane >> 4);
            #pragma unroll
            for (int mt = 0; mt < 4; mt++) {
                const int r = arow0 + mt * 16;
                ldmatrix_x4(a[mt], st + r * 128 + ((ac ^ (r & 7)) * 16));
            }
            // B fragments, paired x4: one x4 covers two adjacent n8 tiles.
            const int brow0 = warp_n * 64 + ((lane >> 4) * 8) + (lane & 7);
            const int bc    = ks * 2 + ((lane >> 3) & 1);
            #pragma unroll
            for (int np = 0; np < 4; np++) {
                const int r = brow0 + np * 16;
                uint32_t tb[4];
                ldmatrix_x4(tb, st + A_TILE_B + r * 128 + ((bc ^ (r & 7)) * 16));
                b[np * 2][0] = tb[0]; b[np * 2][1] = tb[1];
                b[np * 2 + 1][0] = tb[2]; b[np * 2 + 1][1] = tb[3];
            }
            // 32 MMAs per k16 step
            #pragma unroll
            for (int mt = 0; mt < 4; mt++)
                #pragma unroll
                for (int nt = 0; nt < 8; nt++)
                    mma_16816(acc[mt][nt], a[mt], b[nt]);
        }
        __syncthreads();
    }

    // Epilogue: m16n8 acc mapping — c0,c1 row g cols 2q+{0,1}; c2,c3 row g+8.
    const int g = lane >> 2, q = lane & 3;
    #pragma unroll
    for (int mt = 0; mt < 4; mt++) {
        #pragma unroll
        for (int nt = 0; nt < 8; nt++) {
            const int row0 = rowBase + warp_m * 64 + mt * 16 + g;
            const int col  = colBase + warp_n * 64 + nt * 8 + q * 2;
            #pragma unroll
            for (int h = 0; h < 2; h++) {
                const size_t idx = (size_t)(row0 + h * 8) * H_DIM + col;
                float2 add = *reinterpret_cast<const float2*>(addsrc + idx);
                if (MODE == 0) {
                    add.x = fmaxf(add.x, 0.f);
                    add.y = fmaxf(add.y, 0.f);
                }
                float2 o;
                o.x = acc[mt][nt][2 * h + 0] + add.x;
                o.y = acc[mt][nt][2 * h + 1] + add.y;
                *reinterpret_cast<float2*>(C + idx) = o;
            }
        }
    }
}

// ---------------------------------------------------------------------------
// Pipeline:
//   a = fp16(rmsnorm(relu(x), g0));  b = fp16(w0^T)
//   r  = a@b^T + relu(x)
//   a = fp16(rmsnorm(r, g1));        b = fp16(w1^T)
//   r += a@b^T              (in place)
//   out = rmsnorm(r, g2)
// ---------------------------------------------------------------------------
extern "C" void kernel_launch(void* const* d_in, const int* in_sizes, int n_in,
                              void* d_out, int out_size) {
    const float* x  = (const float*)d_in[0];
    const float* g0 = (const float*)d_in[1];
    const float* g1 = (const float*)d_in[2];
    const float* g2 = (const float*)d_in[3];
    const float* w0 = (const float*)d_in[4];
    const float* w1 = (const float*)d_in[5];
    float* out = (float*)d_out;

    __half *a = nullptr, *b = nullptr;
    float* r = nullptr;
    cudaGetSymbolAddress((void**)&a, g_a);
    cudaGetSymbolAddress((void**)&b, g_b);
    cudaGetSymbolAddress((void**)&r, g_r);

    cudaFuncSetAttribute(gemm_mma_kernel<0>, cudaFuncAttributeMaxDynamicSharedMemorySize, GEMM_SMEM_TOTAL);
    cudaFuncSetAttribute(gemm_mma_kernel<1>, cudaFuncAttributeMaxDynamicSharedMemorySize, GEMM_SMEM_TOTAL);

    dim3 gridN(T_DIM);
    dim3 gridT(H_DIM / 32, H_DIM / 32);
    dim3 gridG(H_DIM / 128, T_DIM / 256);
    dim3 blkT(32, 8);

    rmsnorm_h_kernel<true >  <<<gridN, 256>>>(x, g0, a);
    transpose_h_kernel       <<<gridT, blkT>>>(w0, b);
    gemm_mma_kernel<0>       <<<gridG, 256, GEMM_SMEM_TOTAL>>>(a, b, x, r);
    rmsnorm_h_kernel<false>  <<<gridN, 256>>>(r, g1, a);
    transpose_h_kernel       <<<gridT, blkT>>>(w1, b);
    gemm_mma_kernel<1>       <<<gridG, 256, GEMM_SMEM_TOTAL>>>(a, b, r, r);
    rmsnorm_f32_kernel       <<<gridN, 256>>>(r, g2, out);
}

// round 16
// speedup vs baseline: 1.2628x; 1.2628x over previous
#include <cuda_runtime.h>
#include <cuda_fp16.h>
#include <stdint.h>

#define T_DIM 16384
#define H_DIM 4096
#define EPS 1e-5f

// ---------------------------------------------------------------------------
// Scratch (__device__ globals; allocation-free rule)
// ---------------------------------------------------------------------------
__device__ __align__(16) __half g_a [(size_t)T_DIM * H_DIM];  // 128 MB (A fp16)
__device__ __align__(16) float  g_r [(size_t)T_DIM * H_DIM];  // 256 MB
__device__ __align__(16) __half g_b [(size_t)H_DIM * H_DIM];  // 32 MB (B fp16)

// ---------------------------------------------------------------------------
// PTX helpers — family-portable only (ldmatrix / mma.sync / cp.async).
// tcgen05 is rejected by this harness's compute_103 PTX stage (R11 finding).
// ---------------------------------------------------------------------------
__device__ __forceinline__ uint32_t smem_to_u32(const void* p) {
    uint32_t a;
    asm("{ .reg .u64 t; cvta.to.shared.u64 t, %1; cvt.u32.u64 %0, t; }" : "=r"(a) : "l"(p));
    return a;
}
#define CP_ASYNC_16(dst, src) \
    asm volatile("cp.async.cg.shared.global [%0], [%1], 16;" :: "r"(dst), "l"(src))
#define CP_COMMIT() asm volatile("cp.async.commit_group;" ::: "memory")
#define CP_WAIT1()  asm volatile("cp.async.wait_group 1;" ::: "memory")
#define CP_WAIT0()  asm volatile("cp.async.wait_group 0;" ::: "memory")

__device__ __forceinline__ void ldmatrix_x4(uint32_t* r, uint32_t addr) {
    asm volatile("ldmatrix.sync.aligned.m8n8.x4.shared.b16 {%0,%1,%2,%3}, [%4];"
                 : "=r"(r[0]), "=r"(r[1]), "=r"(r[2]), "=r"(r[3]) : "r"(addr));
}
// fp16 MMA, fp32 accumulate
__device__ __forceinline__ void mma_16816(float* c, const uint32_t* a, const uint32_t* b) {
    asm volatile("mma.sync.aligned.m16n8k16.row.col.f32.f16.f16.f32 "
                 "{%0,%1,%2,%3}, {%4,%5,%6,%7}, {%8,%9}, {%0,%1,%2,%3};"
                 : "+f"(c[0]), "+f"(c[1]), "+f"(c[2]), "+f"(c[3])
                 : "r"(a[0]), "r"(a[1]), "r"(a[2]), "r"(a[3]), "r"(b[0]), "r"(b[1]));
}

// ---------------------------------------------------------------------------
// RMSNorm -> fp16 (A operand).
// ---------------------------------------------------------------------------
template<bool RELU_IN>
__global__ void __launch_bounds__(256) rmsnorm_h_kernel(
    const float* __restrict__ in, const float* __restrict__ g,
    __half* __restrict__ oh)
{
    const int row = blockIdx.x;
    const float4* inp = reinterpret_cast<const float4*>(in + (size_t)row * H_DIM);
    const float4* gp  = reinterpret_cast<const float4*>(g);
    uint2* hp = reinterpret_cast<uint2*>(oh + (size_t)row * H_DIM);

    float4 v[4];
    float ssq = 0.f;
    #pragma unroll
    for (int i = 0; i < 4; i++) {
        float4 t = inp[threadIdx.x + i * 256];
        if (RELU_IN) {
            t.x = fmaxf(t.x, 0.f); t.y = fmaxf(t.y, 0.f);
            t.z = fmaxf(t.z, 0.f); t.w = fmaxf(t.w, 0.f);
        }
        v[i] = t;
        ssq += t.x * t.x + t.y * t.y + t.z * t.z + t.w * t.w;
    }

    __shared__ float red[8];
    #pragma unroll
    for (int o = 16; o > 0; o >>= 1) ssq += __shfl_xor_sync(0xffffffffu, ssq, o);
    const int wid = threadIdx.x >> 5, lid = threadIdx.x & 31;
    if (lid == 0) red[wid] = ssq;
    __syncthreads();
    if (wid == 0) {
        float s = (lid < 8) ? red[lid] : 0.f;
        #pragma unroll
        for (int o = 4; o > 0; o >>= 1) s += __shfl_xor_sync(0xffffffffu, s, o);
        if (lid == 0) red[0] = rsqrtf(s * (1.0f / H_DIM) + EPS);
    }
    __syncthreads();
    const float rs = red[0];

    #pragma unroll
    for (int i = 0; i < 4; i++) {
        float4 gg = gp[threadIdx.x + i * 256];
        float4 t = v[i];
        t.x *= rs * gg.x; t.y *= rs * gg.y; t.z *= rs * gg.z; t.w *= rs * gg.w;
        __half h0 = __float2half_rn(t.x), h1 = __float2half_rn(t.y);
        __half h2 = __float2half_rn(t.z), h3 = __float2half_rn(t.w);
        uint2 uh;
        uh.x = (uint32_t)__half_as_ushort(h0) | ((uint32_t)__half_as_ushort(h1) << 16);
        uh.y = (uint32_t)__half_as_ushort(h2) | ((uint32_t)__half_as_ushort(h3) << 16);
        hp[threadIdx.x + i * 256] = uh;
    }
}

// Final RMSNorm -> fp32 out
__global__ void __launch_bounds__(256) rmsnorm_f32_kernel(
    const float* __restrict__ in, const float* __restrict__ g, float* __restrict__ out)
{
    const int row = blockIdx.x;
    const float4* inp  = reinterpret_cast<const float4*>(in + (size_t)row * H_DIM);
    float4*       outp = reinterpret_cast<float4*>(out + (size_t)row * H_DIM);
    const float4* gp   = reinterpret_cast<const float4*>(g);

    float4 v[4];
    float ssq = 0.f;
    #pragma unroll
    for (int i = 0; i < 4; i++) {
        float4 t = inp[threadIdx.x + i * 256];
        v[i] = t;
        ssq += t.x * t.x + t.y * t.y + t.z * t.z + t.w * t.w;
    }
    __shared__ float red[8];
    #pragma unroll
    for (int o = 16; o > 0; o >>= 1) ssq += __shfl_xor_sync(0xffffffffu, ssq, o);
    const int wid = threadIdx.x >> 5, lid = threadIdx.x & 31;
    if (lid == 0) red[wid] = ssq;
    __syncthreads();
    if (wid == 0) {
        float s = (lid < 8) ? red[lid] : 0.f;
        #pragma unroll
        for (int o = 4; o > 0; o >>= 1) s += __shfl_xor_sync(0xffffffffu, s, o);
        if (lid == 0) red[0] = rsqrtf(s * (1.0f / H_DIM) + EPS);
    }
    __syncthreads();
    const float rs = red[0];
    #pragma unroll
    for (int i = 0; i < 4; i++) {
        float4 gg = gp[threadIdx.x + i * 256];
        float4 t = v[i];
        t.x *= rs * gg.x; t.y *= rs * gg.y; t.z *= rs * gg.z; t.w *= rs * gg.w;
        outp[threadIdx.x + i * 256] = t;
    }
}

// ---------------------------------------------------------------------------
// Transpose -> fp16: Bt[n][k] = fp16(w[k][n]).
// ---------------------------------------------------------------------------
__global__ void __launch_bounds__(256) transpose_h_kernel(
    const float* __restrict__ w, __half* __restrict__ b)
{
    __shared__ float tile[32][33];
    const int x  = blockIdx.x * 32 + threadIdx.x;   // n
    const int y0 = blockIdx.y * 32 + threadIdx.y;   // k
    #pragma unroll
    for (int j = 0; j < 4; j++)
        tile[threadIdx.y + 8 * j][threadIdx.x] = w[(size_t)(y0 + 8 * j) * H_DIM + x];
    __syncthreads();
    const int xo = blockIdx.y * 32 + threadIdx.x;   // k
    const int yo = blockIdx.x * 32 + threadIdx.y;   // n
    #pragma unroll
    for (int j = 0; j < 4; j++) {
        float v = tile[threadIdx.x][threadIdx.y + 8 * j];
        b[(size_t)(yo + 8 * j) * H_DIM + xo] = __float2half_rn(v);
    }
}

// ---------------------------------------------------------------------------
// mma.sync fp16 GEMM: C[128x128] = A @ B^T + addend, single pass.
// (R14 config — proven 2645 us; R15's 256x128/1-CTA tile regressed, occupancy
// dominates LDSM pressure on this path.)
//   MODE 0: addend = relu(addsrc);  MODE 1: addend = addsrc (in-place safe)
// 256 threads = 8 warps (4M x 2N), warp tile 32x64, BK=64, 3-stage cp.async.
// Stage = 2 tiles (A, B) x 16 KB = 32 KB; 3 stages = 96 KB -> 2 CTAs/SM.
// Smem rows 128 B, xor-swizzled (chunk16 ^= row&7): conflict-free ldmatrix.
// ONE barrier per chunk: the trailing sync is redundant because the stage
// written at iter i ((i+2)%3 == (i-1)%3) had all its reads completed before
// every thread arrived at iter i's leading barrier (program order + barrier).
// ---------------------------------------------------------------------------
#define BKK 64
#define NCHUNK (H_DIM / BKK)            // 64
#define MTILE_B 16384                   // 128 rows x 128 B
#define STAGE_B (2 * MTILE_B)           // A, B = 32 KB
#define STAGES 3
#define GEMM_SMEM_TOTAL (STAGES * STAGE_B)  // 96 KB

__device__ __forceinline__ void gemm_load_stage(
    uint32_t sbase, int slot, int k0, int tid, int rowBase, int colBase,
    const __half* A, const __half* B)
{
    const char* gsrc[2];
    gsrc[0] = (const char*)(A + (size_t)rowBase * H_DIM + k0);
    gsrc[1] = (const char*)(B + (size_t)colBase * H_DIM + k0);
    const uint32_t stage_base = sbase + slot * STAGE_B;
    #pragma unroll
    for (int t = 0; t < 2; t++) {
        #pragma unroll
        for (int j = 0; j < 4; j++) {           // 1024 16B chunks / 256 thr
            int idx = j * 256 + tid;
            int r = idx >> 3;                   // tile row 0..127
            int c = idx & 7;                    // 16B chunk 0..7
            const char* src = gsrc[t] + (size_t)r * (H_DIM * 2) + c * 16;
            uint32_t dst = stage_base + t * MTILE_B + r * 128 + ((c ^ (r & 7)) * 16);
            CP_ASYNC_16(dst, src);
        }
    }
}

template<int MODE>
__global__ void __launch_bounds__(256, 2) gemm_mma_kernel(
    const __half* __restrict__ A, const __half* __restrict__ B,
    const float* addsrc, float* C)
{
    extern __shared__ char smem[];
    const uint32_t sbase = smem_to_u32(smem);
    const int tid  = threadIdx.x;
    const int lane = tid & 31;
    const int wid  = tid >> 5;
    const int warp_m = wid & 3;     // 0..3  (M)
    const int warp_n = wid >> 2;    // 0..1  (N)

    const int colBase = blockIdx.x * 128;
    const int rowBase = blockIdx.y * 128;

    float acc[2][8][4];
    #pragma unroll
    for (int mt = 0; mt < 2; mt++)
        #pragma unroll
        for (int nt = 0; nt < 8; nt++)
            #pragma unroll
            for (int q = 0; q < 4; q++) acc[mt][nt][q] = 0.f;

    gemm_load_stage(sbase, 0, 0,   tid, rowBase, colBase, A, B);
    CP_COMMIT();
    gemm_load_stage(sbase, 1, BKK, tid, rowBase, colBase, A, B);
    CP_COMMIT();

    for (int i = 0; i < NCHUNK; i++) {
        if (i + 1 < NCHUNK) { CP_WAIT1(); } else { CP_WAIT0(); }
        __syncthreads();    // single barrier per chunk (see header comment)
        if (i + 2 < NCHUNK) {
            gemm_load_stage(sbase, (i + 2) % STAGES, (i + 2) * BKK,
                            tid, rowBase, colBase, A, B);
            CP_COMMIT();
        }

        const uint32_t st = sbase + (i % STAGES) * STAGE_B;
        #pragma unroll
        for (int ks = 0; ks < 4; ks++) {        // four k16 steps in BK=64
            uint32_t a[2][4], b[8][2];

            // A fragments: lanes 0-15 rows m0-15 chunk ks*2; lanes 16-31 +1
            const int arow0 = warp_m * 32 + (lane & 15);
            const int ac    = ks * 2 + (lane >> 4);
            #pragma unroll
            for (int mt = 0; mt < 2; mt++) {
                const int r = arow0 + mt * 16;
                ldmatrix_x4(a[mt], st + r * 128 + ((ac ^ (r & 7)) * 16));
            }
            // B fragments, paired x4: one x4 covers two adjacent n8 tiles.
            const int brow0 = warp_n * 64 + ((lane >> 4) * 8) + (lane & 7);
            const int bc    = ks * 2 + ((lane >> 3) & 1);
            #pragma unroll
            for (int np = 0; np < 4; np++) {
                const int r = brow0 + np * 16;
                uint32_t tb[4];
                ldmatrix_x4(tb, st + MTILE_B + r * 128 + ((bc ^ (r & 7)) * 16));
                b[np * 2][0] = tb[0]; b[np * 2][1] = tb[1];
                b[np * 2 + 1][0] = tb[2]; b[np * 2 + 1][1] = tb[3];
            }
            // single-pass fp16 MMA, fp32 accum
            #pragma unroll
            for (int mt = 0; mt < 2; mt++)
                #pragma unroll
                for (int nt = 0; nt < 8; nt++)
                    mma_16816(acc[mt][nt], a[mt], b[nt]);
        }
    }

    // Epilogue: m16n8 acc mapping — c0,c1 row g cols 2q+{0,1}; c2,c3 row g+8.
    const int g = lane >> 2, q = lane & 3;
    #pragma unroll
    for (int mt = 0; mt < 2; mt++) {
        #pragma unroll
        for (int nt = 0; nt < 8; nt++) {
            const int row0 = rowBase + warp_m * 32 + mt * 16 + g;
            const int col  = colBase + warp_n * 64 + nt * 8 + q * 2;
            #pragma unroll
            for (int h = 0; h < 2; h++) {
                const size_t idx = (size_t)(row0 + h * 8) * H_DIM + col;
                float2 add = *reinterpret_cast<const float2*>(addsrc + idx);
                if (MODE == 0) {
                    add.x = fmaxf(add.x, 0.f);
                    add.y = fmaxf(add.y, 0.f);
                }
                float2 o;
                o.x = acc[mt][nt][2 * h + 0] + add.x;
                o.y = acc[mt][nt][2 * h + 1] + add.y;
                *reinterpret_cast<float2*>(C + idx) = o;
            }
        }
    }
}

// ---------------------------------------------------------------------------
// Pipeline:
//   a = fp16(rmsnorm(relu(x), g0));  b = fp16(w0^T)
//   r  = a@b^T + relu(x)
//   a = fp16(rmsnorm(r, g1));        b = fp16(w1^T)
//   r += a@b^T              (in place)
//   out = rmsnorm(r, g2)
// ---------------------------------------------------------------------------
extern "C" void kernel_launch(void* const* d_in, const int* in_sizes, int n_in,
                              void* d_out, int out_size) {
    const float* x  = (const float*)d_in[0];
    const float* g0 = (const float*)d_in[1];
    const float* g1 = (const float*)d_in[2];
    const float* g2 = (const float*)d_in[3];
    const float* w0 = (const float*)d_in[4];
    const float* w1 = (const float*)d_in[5];
    float* out = (float*)d_out;

    __half *a = nullptr, *b = nullptr;
    float* r = nullptr;
    cudaGetSymbolAddress((void**)&a, g_a);
    cudaGetSymbolAddress((void**)&b, g_b);
    cudaGetSymbolAddress((void**)&r, g_r);

    cudaFuncSetAttribute(gemm_mma_kernel<0>, cudaFuncAttributeMaxDynamicSharedMemorySize, GEMM_SMEM_TOTAL);
    cudaFuncSetAttribute(gemm_mma_kernel<1>, cudaFuncAttributeMaxDynamicSharedMemorySize, GEMM_SMEM_TOTAL);

    dim3 gridN(T_DIM);
    dim3 gridT(H_DIM / 32, H_DIM / 32);
    dim3 gridG(H_DIM / 128, T_DIM / 128);
    dim3 blkT(32, 8);

    rmsnorm_h_kernel<true >  <<<gridN, 256>>>(x, g0, a);
    transpose_h_kernel       <<<gridT, blkT>>>(w0, b);
    gemm_mma_kernel<0>       <<<gridG, 256, GEMM_SMEM_TOTAL>>>(a, b, x, r);
    rmsnorm_h_kernel<false>  <<<gridN, 256>>>(r, g1, a);
    transpose_h_kernel       <<<gridT, blkT>>>(w1, b);
    gemm_mma_kernel<1>       <<<gridG, 256, GEMM_SMEM_TOTAL>>>(a, b, r, r);
    rmsnorm_f32_kernel       <<<gridN, 256>>>(r, g2, out);
}